// round 10
// baseline (speedup 1.0000x reference)
#include <cuda_runtime.h>
#include <cuda_bf16.h>

// DensityLoss: out[b,y,x] = loss[b,y,x] * (fg ? 10 : 1) / (H*W*B),  1/(H*W*B)=2^-23 exact.
// fg = pixel covered by >=1 of 64 boxes (half-open [y1:y2, x1:x2)).
//
// Round 10: decouple mask from stream. Kernel A (warp-per-row) writes each
// row's 1024-bit coverage bitmap to a 1 MB __device__ scratch. Kernel B is a
// pure streaming kernel: no smem, no barriers, ~30 regs -> full occupancy
// (64 warps/SM) with MLP=8 per warp. This breaks the occ-vs-MLP tradeoff
// that capped the fused kernel at ~37% DRAM.

#define B_DIM 8
#define H_DIM 1024
#define W_DIM 1024
#define N_BOX 64

#define NROWS (B_DIM * H_DIM)          // 8192
#define WPR   (W_DIM / 32)             // 32 bitmap words per row

__device__ unsigned g_bm[NROWS * WPR];  // 1 MB static scratch (no allocation)

// ---------------- Kernel A: build per-row coverage bitmaps ----------------
#define A_THREADS 256
#define A_ROWS_PER_CTA 8               // one warp per row

__global__ __launch_bounds__(A_THREADS)
void bitmap_kernel(const int4* __restrict__ bboxes)   // [B, N] (x1,y1,x2,y2)
{
    __shared__ unsigned bm[A_ROWS_PER_CTA][WPR];

    const int t    = threadIdx.x;
    const int lane = t & 31;
    const int r    = t >> 5;
    const int row  = (blockIdx.x << 3) + r;     // b*H + y
    const int b    = row >> 10;
    const int y    = row & (H_DIM - 1);

    bm[r][lane] = 0u;

    const int4* bb = bboxes + (b << 6);
    const int4 b0 = bb[lane];
    const int4 b1 = bb[lane + 32];
    __syncwarp();

    #pragma unroll
    for (int k = 0; k < 2; k++) {
        const int4 bx = k ? b1 : b0;
        const int x1 = min(max(bx.x, 0), W_DIM);
        const int y1 = min(max(bx.y, 0), H_DIM);
        const int x2 = min(max(bx.z, 0), W_DIM);
        const int y2 = min(max(bx.w, 0), H_DIM);
        if (y >= y1 && y < y2 && x1 < x2) {
            const int wA = x1 >> 5;
            const int wB = (x2 - 1) >> 5;
            const unsigned mA = 0xffffffffu << (x1 & 31);
            const unsigned mB = 0xffffffffu >> (31 - ((x2 - 1) & 31));
            if (wA == wB) {
                atomicOr(&bm[r][wA], mA & mB);
            } else {
                atomicOr(&bm[r][wA], mA);
                atomicOr(&bm[r][wB], mB);
                for (int w = wA + 1; w < wB; w++)
                    bm[r][w] = 0xffffffffu;     // same-value race: benign
            }
        }
    }
    __syncwarp();

    g_bm[(row << 5) + lane] = bm[r][lane];      // coalesced 128B per warp
}

// ---------------- Kernel B: pure stream (loss, bm) -> out ----------------
#define S_THREADS 256
#define S_VPT 4                         // float4s per thread
#define NF4 ((NROWS * W_DIM) / 4)       // 2M float4s
#define S_GRID (NF4 / (S_THREADS * S_VPT))   // 2048 CTAs

__global__ __launch_bounds__(S_THREADS)
void stream_kernel(const float4* __restrict__ loss,
                   float4* __restrict__ out)
{
    const int t    = threadIdx.x;
    const int base = blockIdx.x * (S_THREADS * S_VPT) + t;

    // Issue all loads first: 4 x LDG.128 + 4 x LDG.32 in flight.
    float4   l[S_VPT];
    unsigned w[S_VPT];
    #pragma unroll
    for (int i = 0; i < S_VPT; i++) {
        const int f = base + i * S_THREADS;
        l[i] = loss[f];
        w[i] = g_bm[f >> 3];            // word covers 8 float4s; L1-resident
    }

    const float INV = 1.0f / 8388608.0f;   // 2^-23, exact
    const float WFG = 10.0f * INV;
    // (f & 7) == (t & 7): base stride 1024 and i*256 are both 0 mod 8.
    const int shift = (t & 7) << 2;

    #pragma unroll
    for (int i = 0; i < S_VPT; i++) {
        const unsigned nib = w[i] >> shift;
        float4 o;
        o.x = l[i].x * ((nib & 1u) ? WFG : INV);
        o.y = l[i].y * ((nib & 2u) ? WFG : INV);
        o.z = l[i].z * ((nib & 4u) ? WFG : INV);
        o.w = l[i].w * ((nib & 8u) ? WFG : INV);
        out[base + i * S_THREADS] = o;
    }
}

extern "C" void kernel_launch(void* const* d_in, const int* in_sizes, int n_in,
                              void* d_out, int out_size)
{
    const float4* loss   = (const float4*)d_in[0];
    // d_in[1] = pred_densities: unused by the reference computation.
    const int4*   bboxes = (const int4*)d_in[2];
    float4*       out    = (float4*)d_out;

    bitmap_kernel<<<NROWS / A_ROWS_PER_CTA, A_THREADS>>>(bboxes);
    stream_kernel<<<S_GRID, S_THREADS>>>(loss, out);
}

// round 11
// speedup vs baseline: 1.1834x; 1.1834x over previous
#include <cuda_runtime.h>
#include <cuda_bf16.h>

// DensityLoss: out[b,y,x] = loss[b,y,x] * (fg ? 10 : 1) / (H*W*B),  1/(H*W*B)=2^-23 exact.
// fg = pixel covered by >=1 of 64 boxes (half-open [y1:y2, x1:x2)).
//
// Round 11: TMA-streamed single kernel. Per-warp LDG was latency-capped by the
// L1tex wavefront queue (~11.5us plateau, all pipes <40%). Instead each warp
// owns one image row: lane 0 issues a cp.async.bulk (4KB row -> smem) against
// a per-row mbarrier, the warp builds the row's 1024-bit coverage bitmap in
// smem while the bulk copy is in flight, then waits and does 8x
// (LDS.128 -> weight -> STG.128). In-flight bytes/SM = CTAs x 16KB >> latency
// product, so the LTS/DRAM path (not per-warp MLP) becomes the limiter.

#define B_DIM 8
#define H_DIM 1024
#define W_DIM 1024
#define N_BOX 64
#define THREADS 128
#define RPC 4                         // rows per CTA (one warp per row)
#define ROW_BYTES (W_DIM * 4)         // 4096

__global__ __launch_bounds__(THREADS)
void density_loss_kernel(const float* __restrict__ loss,
                         const int4* __restrict__ bboxes,   // [B, N] (x1,y1,x2,y2)
                         float* __restrict__ out)
{
    __shared__ __align__(16) float4 tile[RPC][W_DIM / 4];        // 16 KB
    __shared__ unsigned bm[RPC][W_DIM / 32];                     // 512 B
    __shared__ __align__(8) unsigned long long mbar[RPC];

    const int t    = threadIdx.x;
    const int lane = t & 31;
    const int w    = t >> 5;                    // warp id == row within CTA
    const int row  = (blockIdx.x << 2) + w;     // b*H + y
    const int b    = row >> 10;
    const int y    = row & (H_DIM - 1);

    // ---- init per-row mbarriers (count=1), make visible ----
    if (t < RPC) {
        unsigned mb = (unsigned)__cvta_generic_to_shared(&mbar[t]);
        asm volatile("mbarrier.init.shared.b64 [%0], %1;" :: "r"(mb), "r"(1) : "memory");
    }
    __syncthreads();

    // ---- lane 0 of each warp: launch bulk copy of its row ----
    const unsigned mb = (unsigned)__cvta_generic_to_shared(&mbar[w]);
    if (lane == 0) {
        unsigned dst = (unsigned)__cvta_generic_to_shared(&tile[w][0]);
        const float* src = loss + ((size_t)row << 10);
        asm volatile("mbarrier.arrive.expect_tx.shared.b64 _, [%0], %1;"
                     :: "r"(mb), "r"(ROW_BYTES) : "memory");
        asm volatile("cp.async.bulk.shared::cta.global.mbarrier::complete_tx::bytes "
                     "[%0], [%1], %2, [%3];"
                     :: "r"(dst), "l"(src), "r"(ROW_BYTES), "r"(mb) : "memory");
    }

    // ---- build this row's coverage bitmap (overlaps the bulk copy) ----
    bm[w][lane] = 0u;
    const int4* bb = bboxes + (b << 6);
    const int4 b0 = bb[lane];
    const int4 b1 = bb[lane + 32];
    __syncwarp();

    #pragma unroll
    for (int k = 0; k < 2; k++) {
        const int4 bx = k ? b1 : b0;
        const int x1 = min(max(bx.x, 0), W_DIM);
        const int y1 = min(max(bx.y, 0), H_DIM);
        const int x2 = min(max(bx.z, 0), W_DIM);
        const int y2 = min(max(bx.w, 0), H_DIM);
        if (y >= y1 && y < y2 && x1 < x2) {
            const int wA = x1 >> 5;
            const int wB = (x2 - 1) >> 5;
            const unsigned mA = 0xffffffffu << (x1 & 31);
            const unsigned mB = 0xffffffffu >> (31 - ((x2 - 1) & 31));
            if (wA == wB) {
                atomicOr(&bm[w][wA], mA & mB);
            } else {
                atomicOr(&bm[w][wA], mA);
                atomicOr(&bm[w][wB], mB);
                for (int q = wA + 1; q < wB; q++)
                    bm[w][q] = 0xffffffffu;     // same-value race: benign
            }
        }
    }
    __syncwarp();

    // ---- wait for this row's data (acquire: orders the ld.shared below) ----
    asm volatile(
        "{\n\t"
        ".reg .pred P;\n\t"
        "WAIT_%=:\n\t"
        "mbarrier.try_wait.parity.acquire.cta.shared::cta.b64 P, [%0], 0, 0x989680;\n\t"
        "@P bra DONE_%=;\n\t"
        "bra WAIT_%=;\n\t"
        "DONE_%=:\n\t"
        "}"
        :: "r"(mb) : "memory");

    // ---- stream: smem -> weight -> out ----
    const float INV = 1.0f / 8388608.0f;   // 2^-23, exact
    const float WFG = 10.0f * INV;
    const int shift = (lane & 7) << 2;

    float4* op = reinterpret_cast<float4*>(out + ((size_t)row << 10)) + lane;

    #pragma unroll
    for (int q = 0; q < 8; q++) {
        const float4   l4  = tile[w][(q << 5) + lane];
        const unsigned nib = bm[w][(q << 2) + (lane >> 3)] >> shift;
        float4 o;
        o.x = l4.x * ((nib & 1u) ? WFG : INV);
        o.y = l4.y * ((nib & 2u) ? WFG : INV);
        o.z = l4.z * ((nib & 4u) ? WFG : INV);
        o.w = l4.w * ((nib & 8u) ? WFG : INV);
        op[q << 5] = o;
    }
}

extern "C" void kernel_launch(void* const* d_in, const int* in_sizes, int n_in,
                              void* d_out, int out_size)
{
    const float* loss   = (const float*)d_in[0];
    // d_in[1] = pred_densities: unused by the reference computation.
    const int4*  bboxes = (const int4*)d_in[2];
    float*       out    = (float*)d_out;

    density_loss_kernel<<<(B_DIM * H_DIM) / RPC, THREADS>>>(loss, bboxes, out);
}